// round 8
// baseline (speedup 1.0000x reference)
#include <cuda_runtime.h>
#include <cstddef>
#include <cstdint>

#define LAYERS 5
#define H 128
#define T 2048
#define BATCH 256
#define G 29           // batch groups per layer (grid = 145)
#define BG 9           // rows per group
#define BGP 10         // padded rows (for unguarded reads)
#define BPAD 264       // padded batch rows in staging buffer
#define NTH 1024
#define KS 8           // k-slices
#define KPER 16        // k rows per slice
#define NBMAX 5        // rows per thread (bh0: rows 0-4, bh1: rows 5-9 incl pad)
#define CHUNK 8        // flag publish granularity

typedef unsigned long long ull;

// Inter-layer staging: Xbuf[l][t][row][j] holds output of layer l (l=0..3)
__device__ float Xbuf[(size_t)(LAYERS - 1) * T * BPAD * H];
__device__ int progressFlag[LAYERS * G];

__device__ __forceinline__ ull pack2(float lo, float hi) {
    ull r; asm("mov.b64 %0,{%1,%2};" : "=l"(r) : "f"(lo), "f"(hi)); return r;
}
__device__ __forceinline__ void fma2(ull& acc, ull a, ull b) {
    asm("fma.rn.f32x2 %0,%1,%2,%0;" : "+l"(acc) : "l"(a), "l"(b));
}
__device__ __forceinline__ float lo_of(ull v) {
    return __uint_as_float((unsigned)(v & 0xffffffffull));
}
__device__ __forceinline__ float fast_sigmoid(float x) {
    return 1.0f / (1.0f + __expf(-x));
}
__device__ __forceinline__ int ld_acquire(const int* p) {
    int v; asm volatile("ld.acquire.gpu.s32 %0,[%1];" : "=r"(v) : "l"(p) : "memory"); return v;
}
__device__ __forceinline__ void st_release(int* p, int v) {
    asm volatile("st.release.gpu.s32 [%0],%1;" :: "l"(p), "r"(v) : "memory");
}

struct Smem {
    float partA[KS][3][BG][H];     // 110.6 KB  (partB aliases this region)
    ulonglong2 hx[BGP][H];         //  20.5 KB  {h,h | x,x} per (b,j)
    ull   rh2[BGP][H];             //  10.2 KB  (R*h replicated)
    float zbuf[BG][H];             //   4.6 KB
    float preh[BG][H];             //   4.6 KB
    float br[H];
    float bz[H];
    float bh_[H];
    int   avail_sh;
};                                 // ~149 KB

__global__ void reset_kernel() {
    int i = threadIdx.x;
    if (i < LAYERS * G) progressFlag[i] = 0;
}

__global__ __launch_bounds__(NTH, 1)
void gru_layer_kernel(
    const float* __restrict__ inp,
    const float* __restrict__ W_hr, const float* __restrict__ W_xr, const float* __restrict__ b_r,
    const float* __restrict__ W_hz, const float* __restrict__ W_xz, const float* __restrict__ b_z,
    const float* __restrict__ W_hh, const float* __restrict__ W_xh, const float* __restrict__ b_h,
    float* __restrict__ out)
{
    extern __shared__ char smem_raw[];
    Smem& sm = *reinterpret_cast<Smem*>(smem_raw);
    float* partB = &sm.partA[0][0][0][0];          // [KS][BG][H] alias, disjoint lifetime

    const int bid  = blockIdx.x;
    const int l    = bid / G;
    const int g    = bid % G;
    const int row0 = g * BG;
    const int tid  = threadIdx.x;
    const int jp   = tid & 63;                     // j-pair
    const int j0   = jp << 1;                      // owns cols j0, j0+1
    const int ks   = (tid >> 6) & 7;               // k-slice 0..7
    const int k0   = ks * KPER;
    const int bh2  = tid >> 9;                     // batch half
    const int b0   = bh2 * NBMAX;                  // 0 or 5

    const float* whr = W_hr + l * H * H;
    const float* wxr = W_xr + l * H * H;
    const float* whz = W_hz + l * H * H;
    const float* wxz = W_xz + l * H * H;
    const float* wxh = W_xh + l * H * H;
    const float* whh = W_hh + l * H * H;

    // init: h=0 (incl. pad row), rh2 pad row = 0, biases to smem
    for (int i = tid; i < BGP * H; i += NTH) {
        reinterpret_cast<ulonglong2*>(&sm.hx[0][0])[i] = make_ulonglong2(0ull, 0ull);
        (&sm.rh2[0][0])[i] = 0ull;
    }
    for (int i = tid; i < H; i += NTH) {
        sm.br[i]  = b_r[l * H + i];
        sm.bz[i]  = b_z[l * H + i];
        sm.bh_[i] = b_h[l * H + i];
    }
    __syncthreads();

    int avail = (l == 0) ? T : 0;
    const float* xsrc = (l == 0) ? nullptr : &Xbuf[(size_t)(l - 1) * T * BPAD * H];
    float* ysnk = (l == LAYERS - 1) ? nullptr : &Xbuf[(size_t)l * T * BPAD * H];
    int* myflag  = &progressFlag[l * G + g];
    int* srcflag = (l == 0) ? nullptr : &progressFlag[(l - 1) * G + g];

    for (int t = 0; t < T; ++t) {
        // ---- wait for producer (chunked) ----
        if (t >= avail) {
            if (tid == 0) {
                const int need = t + 1;
                int v = ld_acquire(srcflag);
                while (v < need) { __nanosleep(200); v = ld_acquire(srcflag); }
                sm.avail_sh = v;
            }
            __syncthreads();
            avail = sm.avail_sh;
        }

        // ---- load x_t into hx hi-halves (pad row untouched: stays 0) ----
        for (int i = tid; i < BG * H; i += NTH) {
            const int b = i >> 7, k = i & 127;
            const int row = row0 + b;
            float v;
            if (l == 0) {
                v = (row < BATCH) ? inp[((size_t)row * T + t) * H + k] : 0.0f;
            } else {
                v = xsrc[((size_t)t * BPAD + row) * H + k];
            }
            sm.hx[b][k].y = pack2(v, v);
        }
        __syncthreads();

        // ======== Stage A: r/z/xh preact partials (my k-slice, my b-half) ========
        {
            ull ar[NBMAX], az[NBMAX], ax[NBMAX];
            #pragma unroll
            for (int b = 0; b < NBMAX; ++b) { ar[b] = 0ull; az[b] = 0ull; ax[b] = 0ull; }

            #pragma unroll 2
            for (int kk = 0; kk < KPER; ++kk) {
                const int k = k0 + kk;
                const ull w1 = __ldg(reinterpret_cast<const ull*>(whr + k * H + j0));
                const ull w2 = __ldg(reinterpret_cast<const ull*>(wxr + k * H + j0));
                const ull w3 = __ldg(reinterpret_cast<const ull*>(whz + k * H + j0));
                const ull w4 = __ldg(reinterpret_cast<const ull*>(wxz + k * H + j0));
                const ull w5 = __ldg(reinterpret_cast<const ull*>(wxh + k * H + j0));
                #pragma unroll
                for (int b = 0; b < NBMAX; ++b) {
                    const ulonglong2 hxv = sm.hx[b0 + b][k];   // LDS.128 broadcast
                    fma2(ar[b], w1, hxv.x);
                    fma2(ar[b], w2, hxv.y);
                    fma2(az[b], w3, hxv.x);
                    fma2(az[b], w4, hxv.y);
                    fma2(ax[b], w5, hxv.y);
                }
            }
            #pragma unroll
            for (int b = 0; b < NBMAX; ++b) {
                if (b0 + b < BG) {
                    *reinterpret_cast<ull*>(&sm.partA[ks][0][b0 + b][j0]) = ar[b];
                    *reinterpret_cast<ull*>(&sm.partA[ks][1][b0 + b][j0]) = az[b];
                    *reinterpret_cast<ull*>(&sm.partA[ks][2][b0 + b][j0]) = ax[b];
                }
            }
        }
        __syncthreads();

        // ---- Combine A: reduce 8 slices, activations ----
        for (int i = tid; i < 3 * BG * H; i += NTH) {
            const int g3 = i / (BG * H);
            const int r  = i % (BG * H);
            const int b  = r >> 7;
            const int j  = r & 127;
            float ssum = 0.f;
            #pragma unroll
            for (int ss = 0; ss < KS; ++ss) ssum += sm.partA[ss][g3][b][j];
            if (g3 == 0) {
                const float R  = fast_sigmoid(ssum + sm.br[j]);
                const float rv = R * lo_of(sm.hx[b][j].x);
                sm.rh2[b][j] = pack2(rv, rv);
            } else if (g3 == 1) {
                sm.zbuf[b][j] = fast_sigmoid(ssum + sm.bz[j]);
            } else {
                sm.preh[b][j] = ssum + sm.bh_[j];
            }
        }
        __syncthreads();

        // ======== Stage B: (R*h) @ W_hh partials (partB aliases partA) ========
        {
            ull bh[NBMAX];
            #pragma unroll
            for (int b = 0; b < NBMAX; ++b) bh[b] = 0ull;

            #pragma unroll 4
            for (int kk = 0; kk < KPER; ++kk) {
                const int k = k0 + kk;
                const ull w = __ldg(reinterpret_cast<const ull*>(whh + k * H + j0));
                #pragma unroll
                for (int b = 0; b < NBMAX; ++b)
                    fma2(bh[b], w, sm.rh2[b0 + b][k]);         // LDS.64 broadcast
            }
            #pragma unroll
            for (int b = 0; b < NBMAX; ++b) {
                if (b0 + b < BG)
                    *reinterpret_cast<ull*>(&partB[(ks * BG + b0 + b) * H + j0]) = bh[b];
            }
        }
        __syncthreads();

        // ---- Combine B: tanh + blend, update h, emit ----
        for (int i = tid; i < BG * H; i += NTH) {
            const int b = i >> 7;
            const int j = i & 127;
            float ssum = 0.f;
            #pragma unroll
            for (int ss = 0; ss < KS; ++ss) ssum += partB[(ss * BG + b) * H + j];
            const float htld = tanhf(ssum + sm.preh[b][j]);
            const float Z    = sm.zbuf[b][j];
            const float hv   = lo_of(sm.hx[b][j].x);
            const float hn   = Z * htld + (1.0f - Z) * hv;
            sm.hx[b][j].x = pack2(hn, hn);
            const int row = row0 + b;
            if (l == LAYERS - 1) {
                if (row < BATCH)
                    out[((size_t)row * T + t) * H + j] = hn;
            } else {
                ysnk[((size_t)t * BPAD + row) * H + j] = hn;
            }
        }
        __syncthreads();

        // ---- publish progress (chunked) ----
        if (l < LAYERS - 1 && tid == 0) {
            const int t1 = t + 1;
            if ((t1 & (CHUNK - 1)) == 0 || t1 == T) {
                __threadfence();
                st_release(myflag, t1);
            }
        }
    }
}

extern "C" void kernel_launch(void* const* d_in, const int* in_sizes, int n_in,
                              void* d_out, int out_size) {
    (void)in_sizes; (void)n_in; (void)out_size;
    const float* inp  = (const float*)d_in[0];
    const float* W_hr = (const float*)d_in[1];
    const float* W_xr = (const float*)d_in[2];
    const float* b_r  = (const float*)d_in[3];
    const float* W_hz = (const float*)d_in[4];
    const float* W_xz = (const float*)d_in[5];
    const float* b_z  = (const float*)d_in[6];
    const float* W_hh = (const float*)d_in[7];
    const float* W_xh = (const float*)d_in[8];
    const float* b_h  = (const float*)d_in[9];
    float* out = (float*)d_out;

    reset_kernel<<<1, 256>>>();

    cudaFuncSetAttribute(gru_layer_kernel,
                         cudaFuncAttributeMaxDynamicSharedMemorySize,
                         (int)sizeof(Smem));
    gru_layer_kernel<<<LAYERS * G, NTH, sizeof(Smem)>>>(
        inp, W_hr, W_xr, b_r, W_hz, W_xz, b_z, W_hh, W_xh, b_h, out);
}

// round 9
// speedup vs baseline: 1.3585x; 1.3585x over previous
#include <cuda_runtime.h>
#include <cstddef>
#include <cstdint>

#define LAYERS 5
#define H 128
#define T 2048
#define BATCH 256
#define G 29           // batch groups per layer (grid = 145)
#define BG 9           // rows per group
#define BGP 10         // padded rows
#define BPAD 264       // padded batch rows in staging buffer
#define NTH 512
#define NSLOT 16       // scratch slots (stage A uses 15, stage B uses 16)
#define CHUNK 8        // flag publish granularity

typedef unsigned long long ull;

// Inter-layer staging: Xbuf[l][t][row][j] holds output of layer l (l=0..3)
__device__ float Xbuf[(size_t)(LAYERS - 1) * T * BPAD * H];
__device__ int progressFlag[LAYERS * G];

__device__ __forceinline__ ull pack2(float lo, float hi) {
    ull r; asm("mov.b64 %0,{%1,%2};" : "=l"(r) : "f"(lo), "f"(hi)); return r;
}
__device__ __forceinline__ void fma2(ull& acc, ull a, ull b) {
    asm("fma.rn.f32x2 %0,%1,%2,%0;" : "+l"(acc) : "l"(a), "l"(b));
}
__device__ __forceinline__ float lo_of(ull v) {
    return __uint_as_float((unsigned)(v & 0xffffffffull));
}
__device__ __forceinline__ float fast_sigmoid(float x) {
    return 1.0f / (1.0f + __expf(-x));
}
__device__ __forceinline__ int ld_acquire(const int* p) {
    int v; asm volatile("ld.acquire.gpu.s32 %0,[%1];" : "=r"(v) : "l"(p) : "memory"); return v;
}
__device__ __forceinline__ void st_release(int* p, int v) {
    asm volatile("st.release.gpu.s32 [%0],%1;" :: "l"(p), "r"(v) : "memory");
}

struct Smem {
    float scratch[NSLOT][BG][H];   //  73.7 KB  (stage A partials slots 0-14; stage B slots 0-15)
    ulonglong2 hx[BGP][H];         //  20.5 KB  {h,h | x,x}
    ull   rh2[BGP][H];             //  10.2 KB  (R*h replicated)
    float zbuf[BG][H];             //   4.6 KB
    float preh[BG][H];             //   4.6 KB
    float br[H];
    float bz[H];
    float bh_[H];
    int   avail_sh;
};                                 // ~115 KB

__global__ void reset_kernel() {
    int i = threadIdx.x;
    if (i < LAYERS * G) progressFlag[i] = 0;
}

__global__ __launch_bounds__(NTH, 1)
void gru_layer_kernel(
    const float* __restrict__ inp,
    const float* __restrict__ W_hr, const float* __restrict__ W_xr, const float* __restrict__ b_r,
    const float* __restrict__ W_hz, const float* __restrict__ W_xz, const float* __restrict__ b_z,
    const float* __restrict__ W_hh, const float* __restrict__ W_xh, const float* __restrict__ b_h,
    float* __restrict__ out)
{
    extern __shared__ char smem_raw[];
    Smem& sm = *reinterpret_cast<Smem*>(smem_raw);

    const int bid  = blockIdx.x;
    const int l    = bid / G;
    const int g    = bid % G;
    const int row0 = g * BG;
    const int tid  = threadIdx.x;
    const int wid  = tid >> 5;            // warp 0..15
    const int lane = tid & 31;            // j-quad
    const int j0   = lane << 2;           // owns cols j0..j0+3

    // Stage A role: warps 0..14 -> (matrix m = wid/3, k-third ks = wid%3); warp 15 idle in A
    const int mA   = wid / 3;
    const int ksA  = wid - mA * 3;
    const int k0A  = ksA * 43;
    const int krA  = (ksA == 2) ? 42 : 43;
    // Stage B role: all 16 warps, k-slice of 8
    const int k0B  = wid * 8;

    const float* whr = W_hr + l * H * H;
    const float* wxr = W_xr + l * H * H;
    const float* whz = W_hz + l * H * H;
    const float* wxz = W_xz + l * H * H;
    const float* wxh = W_xh + l * H * H;
    const float* whh = W_hh + l * H * H;

    // Stage-A matrix pointer + whether it multiplies h (lo half) or x (hi half)
    const float* wmat = (mA == 0) ? whr : (mA == 1) ? wxr : (mA == 2) ? whz
                       : (mA == 3) ? wxz : wxh;
    const int hx_off = (mA == 0 || mA == 2) ? 0 : 8;   // byte offset into ulonglong2

    // init
    for (int i = tid; i < BGP * H; i += NTH) {
        reinterpret_cast<ulonglong2*>(&sm.hx[0][0])[i] = make_ulonglong2(0ull, 0ull);
        (&sm.rh2[0][0])[i] = 0ull;
    }
    for (int i = tid; i < H; i += NTH) {
        sm.br[i]  = b_r[l * H + i];
        sm.bz[i]  = b_z[l * H + i];
        sm.bh_[i] = b_h[l * H + i];
    }
    __syncthreads();

    int avail = (l == 0) ? T : 0;
    const float* xsrc = (l == 0) ? nullptr : &Xbuf[(size_t)(l - 1) * T * BPAD * H];
    float* ysnk = (l == LAYERS - 1) ? nullptr : &Xbuf[(size_t)l * T * BPAD * H];
    int* myflag  = &progressFlag[l * G + g];
    int* srcflag = (l == 0) ? nullptr : &progressFlag[(l - 1) * G + g];

    const char* hx_base = reinterpret_cast<const char*>(&sm.hx[0][0]);

    for (int t = 0; t < T; ++t) {
        // ---- wait for producer (chunked) ----
        if (t >= avail) {
            if (tid == 0) {
                const int need = t + 1;
                int v = ld_acquire(srcflag);
                while (v < need) { __nanosleep(200); v = ld_acquire(srcflag); }
                sm.avail_sh = v;
            }
            __syncthreads();
            avail = sm.avail_sh;
        }

        // ---- load x_t into hx hi-halves ----
        for (int i = tid; i < BG * H; i += NTH) {
            const int b = i >> 7, k = i & 127;
            const int row = row0 + b;
            float v;
            if (l == 0) {
                v = (row < BATCH) ? inp[((size_t)row * T + t) * H + k] : 0.0f;
            } else {
                v = xsrc[((size_t)t * BPAD + row) * H + k];
            }
            sm.hx[b][k].y = pack2(v, v);
        }
        __syncthreads();

        // ======== Stage A: partials for my matrix over my k-third (warps 0-14) ========
        if (wid < 15) {
            ull acc[BG][2];
            #pragma unroll
            for (int b = 0; b < BG; ++b) { acc[b][0] = 0ull; acc[b][1] = 0ull; }

            #pragma unroll 4
            for (int kk = 0; kk < krA; ++kk) {
                const int k = k0A + kk;
                const ulonglong2 w =
                    __ldg(reinterpret_cast<const ulonglong2*>(wmat + k * H + j0));
                const char* hp = hx_base + ((size_t)k << 4) + hx_off;   // &hx[0][k] + off
                #pragma unroll
                for (int b = 0; b < BG; ++b) {
                    const ull v = *reinterpret_cast<const ull*>(hp + ((size_t)b * H << 4));
                    fma2(acc[b][0], w.x, v);
                    fma2(acc[b][1], w.y, v);
                }
            }
            #pragma unroll
            for (int b = 0; b < BG; ++b)
                *reinterpret_cast<ulonglong2*>(&sm.scratch[wid][b][j0]) =
                    make_ulonglong2(acc[b][0], acc[b][1]);
        }
        __syncthreads();

        // ---- Combine A: r = slots 0-5, z = slots 6-11, xh = slots 12-14 ----
        for (int i = tid; i < BG * H; i += NTH) {
            const int b = i >> 7;
            const int j = i & 127;
            float rs = 0.f, zs = 0.f, ps = 0.f;
            #pragma unroll
            for (int s = 0; s < 6; ++s)  rs += sm.scratch[s][b][j];
            #pragma unroll
            for (int s = 6; s < 12; ++s) zs += sm.scratch[s][b][j];
            #pragma unroll
            for (int s = 12; s < 15; ++s) ps += sm.scratch[s][b][j];
            const float R  = fast_sigmoid(rs + sm.br[j]);
            const float rv = R * lo_of(sm.hx[b][j].x);
            sm.rh2[b][j]  = pack2(rv, rv);
            sm.zbuf[b][j] = fast_sigmoid(zs + sm.bz[j]);
            sm.preh[b][j] = ps + sm.bh_[j];
        }
        __syncthreads();

        // ======== Stage B: (R*h) @ W_hh, all 16 warps, k-slice of 8 ========
        {
            ull acc[BG][2];
            #pragma unroll
            for (int b = 0; b < BG; ++b) { acc[b][0] = 0ull; acc[b][1] = 0ull; }

            #pragma unroll
            for (int kk = 0; kk < 8; ++kk) {
                const int k = k0B + kk;
                const ulonglong2 w =
                    __ldg(reinterpret_cast<const ulonglong2*>(whh + k * H + j0));
                #pragma unroll
                for (int b = 0; b < BG; ++b) {
                    const ull v = sm.rh2[b][k];     // broadcast LDS.64
                    fma2(acc[b][0], w.x, v);
                    fma2(acc[b][1], w.y, v);
                }
            }
            #pragma unroll
            for (int b = 0; b < BG; ++b)
                *reinterpret_cast<ulonglong2*>(&sm.scratch[wid][b][j0]) =
                    make_ulonglong2(acc[b][0], acc[b][1]);
        }
        __syncthreads();

        // ---- Combine B: sum 16 slots, tanh + blend, update h, emit ----
        for (int i = tid; i < BG * H; i += NTH) {
            const int b = i >> 7;
            const int j = i & 127;
            float ssum = 0.f;
            #pragma unroll
            for (int s = 0; s < NSLOT; ++s) ssum += sm.scratch[s][b][j];
            const float htld = tanhf(ssum + sm.preh[b][j]);
            const float Z    = sm.zbuf[b][j];
            const float hv   = lo_of(sm.hx[b][j].x);
            const float hn   = Z * htld + (1.0f - Z) * hv;
            sm.hx[b][j].x = pack2(hn, hn);
            const int row = row0 + b;
            if (l == LAYERS - 1) {
                if (row < BATCH)
                    out[((size_t)row * T + t) * H + j] = hn;
            } else {
                ysnk[((size_t)t * BPAD + row) * H + j] = hn;
            }
        }
        __syncthreads();

        // ---- publish progress (chunked) ----
        if (l < LAYERS - 1 && tid == 0) {
            const int t1 = t + 1;
            if ((t1 & (CHUNK - 1)) == 0 || t1 == T) {
                __threadfence();
                st_release(myflag, t1);
            }
        }
    }
}

extern "C" void kernel_launch(void* const* d_in, const int* in_sizes, int n_in,
                              void* d_out, int out_size) {
    (void)in_sizes; (void)n_in; (void)out_size;
    const float* inp  = (const float*)d_in[0];
    const float* W_hr = (const float*)d_in[1];
    const float* W_xr = (const float*)d_in[2];
    const float* b_r  = (const float*)d_in[3];
    const float* W_hz = (const float*)d_in[4];
    const float* W_xz = (const float*)d_in[5];
    const float* b_z  = (const float*)d_in[6];
    const float* W_hh = (const float*)d_in[7];
    const float* W_xh = (const float*)d_in[8];
    const float* b_h  = (const float*)d_in[9];
    float* out = (float*)d_out;

    reset_kernel<<<1, 256>>>();

    cudaFuncSetAttribute(gru_layer_kernel,
                         cudaFuncAttributeMaxDynamicSharedMemorySize,
                         (int)sizeof(Smem));
    gru_layer_kernel<<<LAYERS * G, NTH, sizeof(Smem)>>>(
        inp, W_hr, W_xr, b_r, W_hz, W_xz, b_z, W_hh, W_xh, b_h, out);
}